// round 3
// baseline (speedup 1.0000x reference)
#include <cuda_runtime.h>

// Hash-grid 8-neighbor average + 8x8 linear layer.
// x:            [N, 1, 8] float32
// W:            [8, 8]    float32 (out-major: W[o][c])
// b:            [8]       float32
// neighbor_idx: [N, 8]    int32
// out:          [N, 1, 8] float32 = ((1/8) * sum_k x[idx[n,k]]) @ W^T + b
//
// Memory-bound gather kernel: per row, 2x LDG.128 (indices) + 16x LDG.128
// (gathers) + 2x STG.128. All gathers are independent -> MLP ~16-18,
// fully hiding DRAM/L2 latency at 8 warps/block, ~20.5K blocks.

__global__ void __launch_bounds__(256)
hashgrid_avg_linear_kernel(const float* __restrict__ x,
                           const float* __restrict__ W,
                           const float* __restrict__ b,
                           const int*   __restrict__ nidx,
                           float* __restrict__ out,
                           int N)
{
    __shared__ float sW[64];
    __shared__ float sb[8];
    if (threadIdx.x < 64) sW[threadIdx.x] = W[threadIdx.x];
    if (threadIdx.x < 8)  sb[threadIdx.x] = b[threadIdx.x];
    __syncthreads();

    int i = blockIdx.x * blockDim.x + threadIdx.x;
    if (i >= N) return;

    // 8 neighbor indices: 32 bytes, aligned (row stride = 8 ints)
    const int4* ip = reinterpret_cast<const int4*>(nidx + (size_t)i * 8);
    int4 iA = ip[0];
    int4 iB = ip[1];
    int ids[8] = { iA.x, iA.y, iA.z, iA.w, iB.x, iB.y, iB.z, iB.w };

    float acc[8] = {0.f, 0.f, 0.f, 0.f, 0.f, 0.f, 0.f, 0.f};

    // Gather 8 rows of 8 floats each (two float4 loads per row -> 16
    // independent LDG.128 in flight; ptxas front-batches these).
    #pragma unroll
    for (int k = 0; k < 8; k++) {
        const float4* xp = reinterpret_cast<const float4*>(x + (size_t)ids[k] * 8);
        float4 a = xp[0];
        float4 c = xp[1];
        acc[0] += a.x; acc[1] += a.y; acc[2] += a.z; acc[3] += a.w;
        acc[4] += c.x; acc[5] += c.y; acc[6] += c.z; acc[7] += c.w;
    }

    #pragma unroll
    for (int c = 0; c < 8; c++) acc[c] *= 0.125f;

    // 8x8 GEMV: out[o] = b[o] + sum_c acc[c] * W[o*8+c]
    float o[8];
    #pragma unroll
    for (int oo = 0; oo < 8; oo++) {
        float s = sb[oo];
        #pragma unroll
        for (int c = 0; c < 8; c++) s += acc[c] * sW[oo * 8 + c];
        o[oo] = s;
    }

    float4* op = reinterpret_cast<float4*>(out + (size_t)i * 8);
    op[0] = make_float4(o[0], o[1], o[2], o[3]);
    op[1] = make_float4(o[4], o[5], o[6], o[7]);
}

extern "C" void kernel_launch(void* const* d_in, const int* in_sizes, int n_in,
                              void* d_out, int out_size)
{
    // metadata order: x, W, b, neighbor_idx. Select the two small operands
    // (W: 64 elems, b: 8 elems) by size defensively; the two large arrays
    // (x and neighbor_idx, both N*8 elems) keep their positional order.
    const float* x    = nullptr;
    const float* W    = nullptr;
    const float* b    = nullptr;
    const int*   nidx = nullptr;

    for (int k = 0; k < n_in; k++) {
        if (in_sizes[k] == 64 && !W)      W = (const float*)d_in[k];
        else if (in_sizes[k] == 8 && !b)  b = (const float*)d_in[k];
        else if (!x)                      x = (const float*)d_in[k];
        else                              nidx = (const int*)d_in[k];
    }

    float* out = (float*)d_out;
    int N = out_size / 8;   // out is [N, 1, 8] float32

    const int threads = 256;
    int blocks = (N + threads - 1) / threads;
    hashgrid_avg_linear_kernel<<<blocks, threads>>>(x, W, b, nidx, out, N);
}

// round 4
// speedup vs baseline: 1.2621x; 1.2621x over previous
#include <cuda_runtime.h>

// Hash-grid 8-neighbor average + 8x8 linear layer.
// Key structure: entries are ordered cz-fastest per level, so entry i's four
// dz=1 corner indices equal entry i+1's four dz=0 corner indices (verified at
// runtime by exact index comparison). Each lane gathers only its 4 even
// (dz=0) rows and obtains the odd-corner partial sum from lane+1 via shuffle,
// halving L1tex gather wavefronts (the measured bottleneck: L1=94.5%).

__global__ void __launch_bounds__(256)
hashgrid_avg_linear_kernel(const float* __restrict__ x,
                           const float* __restrict__ W,
                           const float* __restrict__ b,
                           const int*   __restrict__ nidx,
                           float* __restrict__ out,
                           int N)
{
    __shared__ float sW[64];
    __shared__ float sb[8];
    if (threadIdx.x < 64) sW[threadIdx.x] = W[threadIdx.x];
    if (threadIdx.x < 8)  sb[threadIdx.x] = b[threadIdx.x];
    __syncthreads();

    const int i0 = blockIdx.x * blockDim.x + threadIdx.x;
    // No early return: every lane participates in the warp shuffles.
    const int i = (i0 < N) ? i0 : (N - 1);
    const unsigned lane = threadIdx.x & 31u;

    // 8 neighbor indices (32 B, aligned, coalesced across the warp)
    const int4* ip = reinterpret_cast<const int4*>(nidx + (size_t)i * 8);
    const int4 iA = ip[0];   // k = 0,1,2,3
    const int4 iB = ip[1];   // k = 4,5,6,7
    // even (dz=0) ids: k=0,2,4,6 -> iA.x, iA.z, iB.x, iB.z
    // odd  (dz=1) ids: k=1,3,5,7 -> iA.y, iA.w, iB.y, iB.w

    // ---- gather the 4 even-corner rows, accumulate sumA ----
    float a0, a1, a2, a3, a4, a5, a6, a7;
    {
        const float4* p0 = reinterpret_cast<const float4*>(x + (size_t)iA.x * 8);
        const float4* p1 = reinterpret_cast<const float4*>(x + (size_t)iA.z * 8);
        const float4* p2 = reinterpret_cast<const float4*>(x + (size_t)iB.x * 8);
        const float4* p3 = reinterpret_cast<const float4*>(x + (size_t)iB.z * 8);
        float4 r0a = p0[0], r0b = p0[1];
        float4 r1a = p1[0], r1b = p1[1];
        float4 r2a = p2[0], r2b = p2[1];
        float4 r3a = p3[0], r3b = p3[1];
        a0 = r0a.x + r1a.x + r2a.x + r3a.x;
        a1 = r0a.y + r1a.y + r2a.y + r3a.y;
        a2 = r0a.z + r1a.z + r2a.z + r3a.z;
        a3 = r0a.w + r1a.w + r2a.w + r3a.w;
        a4 = r0b.x + r1b.x + r2b.x + r3b.x;
        a5 = r0b.y + r1b.y + r2b.y + r3b.y;
        a6 = r0b.z + r1b.z + r2b.z + r3b.z;
        a7 = r0b.w + r1b.w + r2b.w + r3b.w;
    }

    // ---- fetch lane+1's even ids and even-corner sum via shuffle ----
    const unsigned FULL = 0xFFFFFFFFu;
    int n0 = __shfl_down_sync(FULL, iA.x, 1);
    int n2 = __shfl_down_sync(FULL, iA.z, 1);
    int n4 = __shfl_down_sync(FULL, iB.x, 1);
    int n6 = __shfl_down_sync(FULL, iB.z, 1);
    float t0 = __shfl_down_sync(FULL, a0, 1);
    float t1 = __shfl_down_sync(FULL, a1, 1);
    float t2 = __shfl_down_sync(FULL, a2, 1);
    float t3 = __shfl_down_sync(FULL, a3, 1);
    float t4 = __shfl_down_sync(FULL, a4, 1);
    float t5 = __shfl_down_sync(FULL, a5, 1);
    float t6 = __shfl_down_sync(FULL, a6, 1);
    float t7 = __shfl_down_sync(FULL, a7, 1);

    // Sharing holds iff lane+1 is the literal next entry AND its even ids
    // equal my odd ids (exact; hash is deterministic in coords).
    const bool can_share = (lane < 31u) && (i0 + 1 < N) &&
                           (n0 == iA.y) && (n2 == iA.w) &&
                           (n4 == iB.y) && (n6 == iB.w);

    float acc0, acc1, acc2, acc3, acc4, acc5, acc6, acc7;
    if (can_share) {
        acc0 = a0 + t0; acc1 = a1 + t1; acc2 = a2 + t2; acc3 = a3 + t3;
        acc4 = a4 + t4; acc5 = a5 + t5; acc6 = a6 + t6; acc7 = a7 + t7;
    } else {
        // Rare fallback: gather my own 4 odd-corner rows.
        const float4* p0 = reinterpret_cast<const float4*>(x + (size_t)iA.y * 8);
        const float4* p1 = reinterpret_cast<const float4*>(x + (size_t)iA.w * 8);
        const float4* p2 = reinterpret_cast<const float4*>(x + (size_t)iB.y * 8);
        const float4* p3 = reinterpret_cast<const float4*>(x + (size_t)iB.w * 8);
        float4 r0a = p0[0], r0b = p0[1];
        float4 r1a = p1[0], r1b = p1[1];
        float4 r2a = p2[0], r2b = p2[1];
        float4 r3a = p3[0], r3b = p3[1];
        acc0 = a0 + r0a.x + r1a.x + r2a.x + r3a.x;
        acc1 = a1 + r0a.y + r1a.y + r2a.y + r3a.y;
        acc2 = a2 + r0a.z + r1a.z + r2a.z + r3a.z;
        acc3 = a3 + r0a.w + r1a.w + r2a.w + r3a.w;
        acc4 = a4 + r0b.x + r1b.x + r2b.x + r3b.x;
        acc5 = a5 + r0b.y + r1b.y + r2b.y + r3b.y;
        acc6 = a6 + r0b.z + r1b.z + r2b.z + r3b.z;
        acc7 = a7 + r0b.w + r1b.w + r2b.w + r3b.w;
    }

    float y[8] = { acc0 * 0.125f, acc1 * 0.125f, acc2 * 0.125f, acc3 * 0.125f,
                   acc4 * 0.125f, acc5 * 0.125f, acc6 * 0.125f, acc7 * 0.125f };

    // 8x8 GEMV: out[o] = b[o] + sum_c y[c] * W[o*8+c]
    float o[8];
    #pragma unroll
    for (int oo = 0; oo < 8; oo++) {
        float s = sb[oo];
        #pragma unroll
        for (int c = 0; c < 8; c++) s += y[c] * sW[oo * 8 + c];
        o[oo] = s;
    }

    if (i0 < N) {
        float4* op = reinterpret_cast<float4*>(out + (size_t)i0 * 8);
        op[0] = make_float4(o[0], o[1], o[2], o[3]);
        op[1] = make_float4(o[4], o[5], o[6], o[7]);
    }
}

extern "C" void kernel_launch(void* const* d_in, const int* in_sizes, int n_in,
                              void* d_out, int out_size)
{
    // metadata order: x, W, b, neighbor_idx. Select the two small operands
    // (W: 64 elems, b: 8 elems) by size defensively.
    const float* x    = nullptr;
    const float* W    = nullptr;
    const float* b    = nullptr;
    const int*   nidx = nullptr;

    for (int k = 0; k < n_in; k++) {
        if (in_sizes[k] == 64 && !W)      W = (const float*)d_in[k];
        else if (in_sizes[k] == 8 && !b)  b = (const float*)d_in[k];
        else if (!x)                      x = (const float*)d_in[k];
        else                              nidx = (const int*)d_in[k];
    }

    float* out = (float*)d_out;
    int N = out_size / 8;   // out is [N, 1, 8] float32

    const int threads = 256;
    int blocks = (N + threads - 1) / threads;
    hashgrid_avg_linear_kernel<<<blocks, threads>>>(x, W, b, nidx, out, N);
}

// round 5
// speedup vs baseline: 1.4103x; 1.1174x over previous
#include <cuda_runtime.h>

// Hash-grid 8-neighbor average + 8x8 linear layer.
//
// Two L1tex-wavefront optimizations (L1 is the measured bottleneck):
//  1. z-sharing: entry e's four odd (dz=1) corner indices equal entry e+1's
//     even (dz=0) corner indices (validated exactly per entry); so each entry
//     gathers only its 4 even rows and gets the odd contribution via shuffle.
//  2. pair-split: lanes (2p, 2p+1) cooperatively gather the pair's 8 even
//     rows; in each LDG the two lanes load the low/high 16B half of the SAME
//     32B row -> same 128B line -> 16 distinct lines per instr instead of 32.

__global__ void __launch_bounds__(256)
hashgrid_avg_linear_kernel(const float* __restrict__ x,
                           const float* __restrict__ W,
                           const float* __restrict__ b,
                           const int*   __restrict__ nidx,
                           float* __restrict__ out,
                           int N)
{
    __shared__ float sW[64];
    __shared__ float sb[8];
    if (threadIdx.x < 64) sW[threadIdx.x] = W[threadIdx.x];
    if (threadIdx.x < 8)  sb[threadIdx.x] = b[threadIdx.x];
    __syncthreads();

    const unsigned FULL = 0xFFFFFFFFu;
    const int i0 = blockIdx.x * blockDim.x + threadIdx.x;
    const int i  = (i0 < N) ? i0 : (N - 1);   // tail clamp; all lanes shuffle
    const unsigned lane = threadIdx.x & 31u;
    const int s = (int)(lane & 1u);           // half selector within pair

    // Coalesced index load: 8 ints per entry.
    const int4* ip = reinterpret_cast<const int4*>(nidx + (size_t)i * 8);
    const int4 iA = ip[0];
    const int4 iB = ip[1];
    // even (dz=0) ids: k=0,2,4,6 ; odd (dz=1) ids: k=1,3,5,7
    const int e0 = iA.x, e1 = iA.z, e2 = iB.x, e3 = iB.z;
    const int o0 = iA.y, o1 = iA.w, o2 = iB.y, o3 = iB.w;

    // Partner's even ids (lane^1).
    const int p0 = __shfl_xor_sync(FULL, e0, 1);
    const int p1 = __shfl_xor_sync(FULL, e1, 1);
    const int p2 = __shfl_xor_sync(FULL, e2, 1);
    const int p3 = __shfl_xor_sync(FULL, e3, 1);

    // Rows of the pair's EVEN-lane entry (2p) and ODD-lane entry (2p+1).
    const int rA0 = s ? p0 : e0, rA1 = s ? p1 : e1, rA2 = s ? p2 : e2, rA3 = s ? p3 : e3;
    const int rB0 = s ? e0 : p0, rB1 = s ? e1 : p1, rB2 = s ? e2 : p2, rB3 = s ? e3 : p3;

    // 8 half-row gathers; lane loads its 16B half (offset 4*s floats).
    const size_t hs = (size_t)(4 * s);
    const float4 gA0 = *reinterpret_cast<const float4*>(x + (size_t)rA0 * 8 + hs);
    const float4 gA1 = *reinterpret_cast<const float4*>(x + (size_t)rA1 * 8 + hs);
    const float4 gA2 = *reinterpret_cast<const float4*>(x + (size_t)rA2 * 8 + hs);
    const float4 gA3 = *reinterpret_cast<const float4*>(x + (size_t)rA3 * 8 + hs);
    const float4 gB0 = *reinterpret_cast<const float4*>(x + (size_t)rB0 * 8 + hs);
    const float4 gB1 = *reinterpret_cast<const float4*>(x + (size_t)rB1 * 8 + hs);
    const float4 gB2 = *reinterpret_cast<const float4*>(x + (size_t)rB2 * 8 + hs);
    const float4 gB3 = *reinterpret_cast<const float4*>(x + (size_t)rB3 * 8 + hs);

    // Half even-sums: SA = entry 2p (channels 4s..4s+3), SB = entry 2p+1.
    float SA0 = gA0.x + gA1.x + gA2.x + gA3.x;
    float SA1 = gA0.y + gA1.y + gA2.y + gA3.y;
    float SA2 = gA0.z + gA1.z + gA2.z + gA3.z;
    float SA3 = gA0.w + gA1.w + gA2.w + gA3.w;
    float SB0 = gB0.x + gB1.x + gB2.x + gB3.x;
    float SB1 = gB0.y + gB1.y + gB2.y + gB3.y;
    float SB2 = gB0.z + gB1.z + gB2.z + gB3.z;
    float SB3 = gB0.w + gB1.w + gB2.w + gB3.w;

    // Exchange the half that belongs to the partner's entry.
    float x0 = s ? SA0 : SB0, x1 = s ? SA1 : SB1;
    float x2 = s ? SA2 : SB2, x3 = s ? SA3 : SB3;
    const float r0 = __shfl_xor_sync(FULL, x0, 1);
    const float r1 = __shfl_xor_sync(FULL, x1, 1);
    const float r2 = __shfl_xor_sync(FULL, x2, 1);
    const float r3 = __shfl_xor_sync(FULL, x3, 1);

    // Full even-sum of MY entry (lane s==0 -> entry 2p, s==1 -> entry 2p+1).
    float ev[8];
    ev[0] = s ? r0 : SA0;  ev[1] = s ? r1 : SA1;
    ev[2] = s ? r2 : SA2;  ev[3] = s ? r3 : SA3;
    ev[4] = s ? SB0 : r0;  ev[5] = s ? SB1 : r1;
    ev[6] = s ? SB2 : r2;  ev[7] = s ? SB3 : r3;

    // z-share: next lane's even ids + even-sum.
    const int n0 = __shfl_down_sync(FULL, e0, 1);
    const int n1 = __shfl_down_sync(FULL, e1, 1);
    const int n2 = __shfl_down_sync(FULL, e2, 1);
    const int n3 = __shfl_down_sync(FULL, e3, 1);
    float t[8];
    #pragma unroll
    for (int c = 0; c < 8; c++) t[c] = __shfl_down_sync(FULL, ev[c], 1);

    const bool can_share = (lane < 31u) && (i0 + 1 < N) &&
                           (n0 == o0) && (n1 == o1) && (n2 == o2) && (n3 == o3);

    float acc[8];
    if (can_share) {
        #pragma unroll
        for (int c = 0; c < 8; c++) acc[c] = ev[c] + t[c];
    } else {
        // Rare fallback (~3-4% of lanes): gather my own 4 odd rows fully.
        const float4* q0 = reinterpret_cast<const float4*>(x + (size_t)o0 * 8);
        const float4* q1 = reinterpret_cast<const float4*>(x + (size_t)o1 * 8);
        const float4* q2 = reinterpret_cast<const float4*>(x + (size_t)o2 * 8);
        const float4* q3 = reinterpret_cast<const float4*>(x + (size_t)o3 * 8);
        float4 u0 = q0[0], v0 = q0[1];
        float4 u1 = q1[0], v1 = q1[1];
        float4 u2 = q2[0], v2 = q2[1];
        float4 u3 = q3[0], v3 = q3[1];
        acc[0] = ev[0] + u0.x + u1.x + u2.x + u3.x;
        acc[1] = ev[1] + u0.y + u1.y + u2.y + u3.y;
        acc[2] = ev[2] + u0.z + u1.z + u2.z + u3.z;
        acc[3] = ev[3] + u0.w + u1.w + u2.w + u3.w;
        acc[4] = ev[4] + v0.x + v1.x + v2.x + v3.x;
        acc[5] = ev[5] + v0.y + v1.y + v2.y + v3.y;
        acc[6] = ev[6] + v0.z + v1.z + v2.z + v3.z;
        acc[7] = ev[7] + v0.w + v1.w + v2.w + v3.w;
    }

    float y[8];
    #pragma unroll
    for (int c = 0; c < 8; c++) y[c] = acc[c] * 0.125f;

    // 8x8 GEMV: out[o] = b[o] + sum_c y[c] * W[o*8+c]
    float o[8];
    #pragma unroll
    for (int oo = 0; oo < 8; oo++) {
        float acc_o = sb[oo];
        #pragma unroll
        for (int c = 0; c < 8; c++) acc_o += y[c] * sW[oo * 8 + c];
        o[oo] = acc_o;
    }

    if (i0 < N) {
        float4* op = reinterpret_cast<float4*>(out + (size_t)i0 * 8);
        op[0] = make_float4(o[0], o[1], o[2], o[3]);
        op[1] = make_float4(o[4], o[5], o[6], o[7]);
    }
}

extern "C" void kernel_launch(void* const* d_in, const int* in_sizes, int n_in,
                              void* d_out, int out_size)
{
    // metadata order: x, W, b, neighbor_idx. Select the two small operands
    // (W: 64 elems, b: 8 elems) by size defensively.
    const float* x    = nullptr;
    const float* W    = nullptr;
    const float* b    = nullptr;
    const int*   nidx = nullptr;

    for (int k = 0; k < n_in; k++) {
        if (in_sizes[k] == 64 && !W)      W = (const float*)d_in[k];
        else if (in_sizes[k] == 8 && !b)  b = (const float*)d_in[k];
        else if (!x)                      x = (const float*)d_in[k];
        else                              nidx = (const int*)d_in[k];
    }

    float* out = (float*)d_out;
    int N = out_size / 8;   // out is [N, 1, 8] float32

    const int threads = 256;
    int blocks = (N + threads - 1) / threads;
    hashgrid_avg_linear_kernel<<<blocks, threads>>>(x, W, b, nidx, out, N);
}

// round 8
// speedup vs baseline: 1.5288x; 1.0841x over previous
#include <cuda_runtime.h>

// Hash-grid 8-neighbor average + 8x8 linear layer.
//
// L1tex-wavefront optimizations (L1 is the measured bottleneck, 80.7%):
//  1. z-sharing: entry e's four odd (dz=1) corner indices equal entry e+1's
//     even (dz=0) corner indices (validated exactly per entry); each entry
//     gathers only its 4 even rows, odd contribution comes via shuffle.
//  2. pair-split: lanes (2p, 2p+1) cooperatively gather the pair's 8 even
//     rows; the two lanes load the low/high 16B half of the SAME 32B row in
//     one LDG -> 16 distinct lines per instr instead of 32.
//  3. W/b in __constant__ memory: GEMV coefficient reads go through the
//     uniform/constant port (LDCU), not L1tex. No shared mem, no barrier.

__constant__ float cW[64];
__constant__ float cb[8];

__global__ void __launch_bounds__(256)
hashgrid_avg_linear_kernel(const float* __restrict__ x,
                           const int*   __restrict__ nidx,
                           float* __restrict__ out,
                           int N)
{
    const unsigned FULL = 0xFFFFFFFFu;
    const int i0 = blockIdx.x * blockDim.x + threadIdx.x;
    const int i  = (i0 < N) ? i0 : (N - 1);   // tail clamp; all lanes shuffle
    const unsigned lane = threadIdx.x & 31u;
    const int s = (int)(lane & 1u);           // half selector within pair

    // Coalesced index load: 8 ints per entry.
    const int4* ip = reinterpret_cast<const int4*>(nidx + (size_t)i * 8);
    const int4 iA = ip[0];
    const int4 iB = ip[1];
    // even (dz=0) ids: k=0,2,4,6 ; odd (dz=1) ids: k=1,3,5,7
    const int e0 = iA.x, e1 = iA.z, e2 = iB.x, e3 = iB.z;
    const int o0 = iA.y, o1 = iA.w, o2 = iB.y, o3 = iB.w;

    // Partner's even ids (lane^1).
    const int p0 = __shfl_xor_sync(FULL, e0, 1);
    const int p1 = __shfl_xor_sync(FULL, e1, 1);
    const int p2 = __shfl_xor_sync(FULL, e2, 1);
    const int p3 = __shfl_xor_sync(FULL, e3, 1);

    // Rows of the pair's EVEN-lane entry (2p) and ODD-lane entry (2p+1).
    const int rA0 = s ? p0 : e0, rA1 = s ? p1 : e1, rA2 = s ? p2 : e2, rA3 = s ? p3 : e3;
    const int rB0 = s ? e0 : p0, rB1 = s ? e1 : p1, rB2 = s ? e2 : p2, rB3 = s ? e3 : p3;

    // 8 half-row gathers; lane loads its 16B half (offset 4*s floats).
    const size_t hs = (size_t)(4 * s);
    const float4 gA0 = *reinterpret_cast<const float4*>(x + (size_t)rA0 * 8 + hs);
    const float4 gA1 = *reinterpret_cast<const float4*>(x + (size_t)rA1 * 8 + hs);
    const float4 gA2 = *reinterpret_cast<const float4*>(x + (size_t)rA2 * 8 + hs);
    const float4 gA3 = *reinterpret_cast<const float4*>(x + (size_t)rA3 * 8 + hs);
    const float4 gB0 = *reinterpret_cast<const float4*>(x + (size_t)rB0 * 8 + hs);
    const float4 gB1 = *reinterpret_cast<const float4*>(x + (size_t)rB1 * 8 + hs);
    const float4 gB2 = *reinterpret_cast<const float4*>(x + (size_t)rB2 * 8 + hs);
    const float4 gB3 = *reinterpret_cast<const float4*>(x + (size_t)rB3 * 8 + hs);

    // Half even-sums: SA = entry 2p (channels 4s..4s+3), SB = entry 2p+1.
    float SA0 = gA0.x + gA1.x + gA2.x + gA3.x;
    float SA1 = gA0.y + gA1.y + gA2.y + gA3.y;
    float SA2 = gA0.z + gA1.z + gA2.z + gA3.z;
    float SA3 = gA0.w + gA1.w + gA2.w + gA3.w;
    float SB0 = gB0.x + gB1.x + gB2.x + gB3.x;
    float SB1 = gB0.y + gB1.y + gB2.y + gB3.y;
    float SB2 = gB0.z + gB1.z + gB2.z + gB3.z;
    float SB3 = gB0.w + gB1.w + gB2.w + gB3.w;

    // Exchange the half that belongs to the partner's entry.
    float x0 = s ? SA0 : SB0, x1 = s ? SA1 : SB1;
    float x2 = s ? SA2 : SB2, x3 = s ? SA3 : SB3;
    const float r0 = __shfl_xor_sync(FULL, x0, 1);
    const float r1 = __shfl_xor_sync(FULL, x1, 1);
    const float r2 = __shfl_xor_sync(FULL, x2, 1);
    const float r3 = __shfl_xor_sync(FULL, x3, 1);

    // Full even-sum of MY entry (lane s==0 -> entry 2p, s==1 -> entry 2p+1).
    float ev[8];
    ev[0] = s ? r0 : SA0;  ev[1] = s ? r1 : SA1;
    ev[2] = s ? r2 : SA2;  ev[3] = s ? r3 : SA3;
    ev[4] = s ? SB0 : r0;  ev[5] = s ? SB1 : r1;
    ev[6] = s ? SB2 : r2;  ev[7] = s ? SB3 : r3;

    // z-share: next lane's even ids + even-sum.
    const int n0 = __shfl_down_sync(FULL, e0, 1);
    const int n1 = __shfl_down_sync(FULL, e1, 1);
    const int n2 = __shfl_down_sync(FULL, e2, 1);
    const int n3 = __shfl_down_sync(FULL, e3, 1);
    float t[8];
    #pragma unroll
    for (int c = 0; c < 8; c++) t[c] = __shfl_down_sync(FULL, ev[c], 1);

    const bool can_share = (lane < 31u) && (i0 + 1 < N) &&
                           (n0 == o0) && (n1 == o1) && (n2 == o2) && (n3 == o3);

    float acc[8];
    if (can_share) {
        #pragma unroll
        for (int c = 0; c < 8; c++) acc[c] = ev[c] + t[c];
    } else {
        // Rare fallback (~3-4% of lanes): gather my own 4 odd rows fully.
        const float4* q0 = reinterpret_cast<const float4*>(x + (size_t)o0 * 8);
        const float4* q1 = reinterpret_cast<const float4*>(x + (size_t)o1 * 8);
        const float4* q2 = reinterpret_cast<const float4*>(x + (size_t)o2 * 8);
        const float4* q3 = reinterpret_cast<const float4*>(x + (size_t)o3 * 8);
        float4 u0 = q0[0], v0 = q0[1];
        float4 u1 = q1[0], v1 = q1[1];
        float4 u2 = q2[0], v2 = q2[1];
        float4 u3 = q3[0], v3 = q3[1];
        acc[0] = ev[0] + u0.x + u1.x + u2.x + u3.x;
        acc[1] = ev[1] + u0.y + u1.y + u2.y + u3.y;
        acc[2] = ev[2] + u0.z + u1.z + u2.z + u3.z;
        acc[3] = ev[3] + u0.w + u1.w + u2.w + u3.w;
        acc[4] = ev[4] + v0.x + v1.x + v2.x + v3.x;
        acc[5] = ev[5] + v0.y + v1.y + v2.y + v3.y;
        acc[6] = ev[6] + v0.z + v1.z + v2.z + v3.z;
        acc[7] = ev[7] + v0.w + v1.w + v2.w + v3.w;
    }

    float y[8];
    #pragma unroll
    for (int c = 0; c < 8; c++) y[c] = acc[c] * 0.125f;

    // 8x8 GEMV with constant-bank coefficients (uniform port, no L1tex).
    float o[8];
    #pragma unroll
    for (int oo = 0; oo < 8; oo++) {
        float acc_o = cb[oo];
        #pragma unroll
        for (int c = 0; c < 8; c++) acc_o += y[c] * cW[oo * 8 + c];
        o[oo] = acc_o;
    }

    if (i0 < N) {
        float4* op = reinterpret_cast<float4*>(out + (size_t)i0 * 8);
        op[0] = make_float4(o[0], o[1], o[2], o[3]);
        op[1] = make_float4(o[4], o[5], o[6], o[7]);
    }
}

extern "C" void kernel_launch(void* const* d_in, const int* in_sizes, int n_in,
                              void* d_out, int out_size)
{
    // metadata order: x, W, b, neighbor_idx. Select the two small operands
    // (W: 64 elems, b: 8 elems) by size defensively.
    const float* x    = nullptr;
    const float* W    = nullptr;
    const float* b    = nullptr;
    const int*   nidx = nullptr;

    for (int k = 0; k < n_in; k++) {
        if (in_sizes[k] == 64 && !W)      W = (const float*)d_in[k];
        else if (in_sizes[k] == 8 && !b)  b = (const float*)d_in[k];
        else if (!x)                      x = (const float*)d_in[k];
        else                              nidx = (const int*)d_in[k];
    }

    float* out = (float*)d_out;
    int N = out_size / 8;   // out is [N, 1, 8] float32

    // Device-to-device async copies into constant bank: graph-capturable
    // memcpy nodes, no allocation, deterministic.
    cudaMemcpyToSymbolAsync(cW, W, 64 * sizeof(float), 0, cudaMemcpyDeviceToDevice);
    cudaMemcpyToSymbolAsync(cb, b,  8 * sizeof(float), 0, cudaMemcpyDeviceToDevice);

    const int threads = 256;
    int blocks = (N + threads - 1) / threads;
    hashgrid_avg_linear_kernel<<<blocks, threads>>>(x, nidx, out, N);
}